// round 9
// baseline (speedup 1.0000x reference)
#include <cuda_runtime.h>
#include <cuda_bf16.h>
#include <cstdint>
#include <math.h>

// ---------------------------------------------------------------------------
// Problem constants
// ---------------------------------------------------------------------------
#define NPATCH 1800            // B(8) * L(225)
#define NTOK   64              // k*k
#define CDIM   256
#define QKVDIM 768
#define MROWS  (NPATCH * NTOK) // 115200
#define SCALE_ATT 0.17677669529663687f

// ---------------------------------------------------------------------------
// Global scratch.
//  g_qh/g_ql : qkv hi/lo bf16 planes (GEMM1 out / attn in). g_qh re-used
//              (as float*) for y, the GEMM2 fp32 output.
//  g_phi/g_plo : h hi/lo (LN out / GEMM1 A), then o hi/lo (attn out / GEMM2 A)
// ---------------------------------------------------------------------------
__device__ __nv_bfloat16  g_qh[(size_t)MROWS * QKVDIM];   // 177 MB
__device__ __nv_bfloat16  g_ql[(size_t)MROWS * QKVDIM];   // 177 MB
__device__ __nv_bfloat16  g_phi[(size_t)MROWS * CDIM];    // 59 MB
__device__ __nv_bfloat16  g_plo[(size_t)MROWS * CDIM];    // 59 MB
__device__ __nv_bfloat16  g_wqT_hi[QKVDIM * CDIM];
__device__ __nv_bfloat16  g_wqT_lo[QKVDIM * CDIM];
__device__ __nv_bfloat16  g_woT_hi[CDIM * CDIM];
__device__ __nv_bfloat16  g_woT_lo[CDIM * CDIM];

// ---------------------------------------------------------------------------
// Helpers
// ---------------------------------------------------------------------------
__device__ __forceinline__ uint32_t smem_to_u32(const void* p) {
    uint32_t a;
    asm("{ .reg .u64 t; cvta.to.shared.u64 t, %1; cvt.u32.u64 %0, t; }"
        : "=r"(a) : "l"(p));
    return a;
}
__device__ __forceinline__ float warp_sum(float v) {
#pragma unroll
    for (int o = 16; o; o >>= 1) v += __shfl_xor_sync(0xffffffffu, v, o);
    return v;
}
__device__ __forceinline__ void split_bf16(float v, __nv_bfloat16& hi, __nv_bfloat16& lo) {
    hi = __float2bfloat16(v);
    lo = __float2bfloat16(v - __bfloat162float(hi));
}
__device__ __forceinline__ void ldsm_x4(uint32_t addr, uint32_t& r0, uint32_t& r1,
                                        uint32_t& r2, uint32_t& r3) {
    asm volatile("ldmatrix.sync.aligned.m8n8.x4.shared.b16 {%0,%1,%2,%3}, [%4];"
                 : "=r"(r0), "=r"(r1), "=r"(r2), "=r"(r3) : "r"(addr));
}
__device__ __forceinline__ void ldsm_x4_t(uint32_t addr, uint32_t* r) {
    asm volatile("ldmatrix.sync.aligned.m8n8.x4.trans.shared.b16 {%0,%1,%2,%3}, [%4];"
                 : "=r"(r[0]), "=r"(r[1]), "=r"(r[2]), "=r"(r[3]) : "r"(addr));
}
__device__ __forceinline__ void mma_bf16(float* d, const uint32_t* a,
                                         uint32_t b0, uint32_t b1) {
    asm volatile(
        "mma.sync.aligned.m16n8k16.row.col.f32.bf16.bf16.f32 "
        "{%0,%1,%2,%3}, {%4,%5,%6,%7}, {%8,%9}, {%0,%1,%2,%3};"
        : "+f"(d[0]), "+f"(d[1]), "+f"(d[2]), "+f"(d[3])
        : "r"(a[0]), "r"(a[1]), "r"(a[2]), "r"(a[3]), "r"(b0), "r"(b1));
}
__device__ __forceinline__ uint32_t pack_split(float c0, float c1, float& r0, float& r1) {
    __nv_bfloat162 t = __floats2bfloat162_rn(c0, c1);
    r0 = c0 - __bfloat162float(t.x);
    r1 = c1 - __bfloat162float(t.y);
    return *reinterpret_cast<uint32_t*>(&t);
}
__device__ __forceinline__ uint32_t pack2(float c0, float c1) {
    __nv_bfloat162 t = __floats2bfloat162_rn(c0, c1);
    return *reinterpret_cast<uint32_t*>(&t);
}
__device__ __forceinline__ void cp_async16(uint32_t saddr, const void* gaddr) {
    asm volatile("cp.async.cg.shared.global [%0], [%1], 16;" :: "r"(saddr), "l"(gaddr));
}
__device__ __forceinline__ void cp_commit() {
    asm volatile("cp.async.commit_group;" ::: "memory");
}
template<int N>
__device__ __forceinline__ void cp_wait() {
    asm volatile("cp.async.wait_group %0;" :: "n"(N) : "memory");
}

// ---------------------------------------------------------------------------
// Kernel 0: transpose + hi/lo split of the two weight matrices
// ---------------------------------------------------------------------------
__global__ __launch_bounds__(256) void k_split_w(
    const float* __restrict__ wqkv, const float* __restrict__ wout,
    __nv_bfloat16* __restrict__ qT_hi, __nv_bfloat16* __restrict__ qT_lo,
    __nv_bfloat16* __restrict__ oT_hi, __nv_bfloat16* __restrict__ oT_lo)
{
    int e = blockIdx.x * 256 + threadIdx.x;
    if (e < QKVDIM * CDIM) {
        int n = e >> 8, k = e & 255;
        __nv_bfloat16 h, l;
        split_bf16(wqkv[k * QKVDIM + n], h, l);
        qT_hi[e] = h; qT_lo[e] = l;
    } else {
        int e2 = e - QKVDIM * CDIM;
        if (e2 < CDIM * CDIM) {
            int n = e2 >> 8, k = e2 & 255;
            __nv_bfloat16 h, l;
            split_bf16(wout[k * CDIM + n], h, l);
            oT_hi[e2] = h; oT_lo[e2] = l;
        }
    }
}

// ---------------------------------------------------------------------------
// Kernel 1: gather patches + LayerNorm x2, emit hi/lo bf16 planes
// ---------------------------------------------------------------------------
__global__ __launch_bounds__(256) void k_gather_ln(
    const float* __restrict__ x,
    const float* __restrict__ g1, const float* __restrict__ b1,
    const float* __restrict__ g2, const float* __restrict__ b2,
    __nv_bfloat16* __restrict__ hhi, __nv_bfloat16* __restrict__ hlo)
{
    int warp = threadIdx.x >> 5, lane = threadIdx.x & 31;
    int row = blockIdx.x * 8 + warp;
    int p = row >> 6, t = row & 63;
    int b = p / 225, l = p - b * 225;
    int ph = l / 15, pw = l - ph * 15;
    int gr = ph * 4 + (t >> 3);
    int gc = pw * 4 + (t & 7);
    const float* xr = x + (((size_t)(b * 64 + gr)) * 64 + gc) * 256;

    float v[8];
    float s = 0.f;
#pragma unroll
    for (int i = 0; i < 8; i++) { v[i] = xr[lane + i * 32]; s += v[i]; }
    s = warp_sum(s);
    float mean = s * (1.f / 256.f);
    float vs = 0.f;
#pragma unroll
    for (int i = 0; i < 8; i++) { v[i] -= mean; vs += v[i] * v[i]; }
    vs = warp_sum(vs);
    float inv = rsqrtf(vs * (1.f / 256.f) + 1e-5f);

    float s2 = 0.f;
#pragma unroll
    for (int i = 0; i < 8; i++) {
        v[i] = v[i] * inv * g1[lane + i * 32] + b1[lane + i * 32];
        s2 += v[i];
    }
    s2 = warp_sum(s2);
    float mean2 = s2 * (1.f / 256.f);
    float vs2 = 0.f;
#pragma unroll
    for (int i = 0; i < 8; i++) { v[i] -= mean2; vs2 += v[i] * v[i]; }
    vs2 = warp_sum(vs2);
    float inv2 = rsqrtf(vs2 * (1.f / 256.f) + 1e-5f);

    size_t base = (size_t)row * 256;
#pragma unroll
    for (int i = 0; i < 8; i++) {
        float val = v[i] * inv2 * g2[lane + i * 32] + b2[lane + i * 32];
        __nv_bfloat16 h, lo;
        split_bf16(val, h, lo);
        hhi[base + lane + i * 32] = h;
        hlo[base + lane + i * 32] = lo;
    }
}

// ---------------------------------------------------------------------------
// mma.sync GEMM with cp.async double-buffered pipeline (measured neutral vs
// sync loads; kept). C = (Ahi+Alo)[M,256] @ (Bhi+Blo)[N,256]^T, 3 products.
// ---------------------------------------------------------------------------
#define ASTRIDE 40
#define PLANE_E (128 * ASTRIDE)
#define TILE_E  (4 * PLANE_E)
#define GEMM_SM_BYTES (2 * TILE_E * 2) // 81920 B

__global__ __launch_bounds__(256, 2) void k_mma_gemm(
    const __nv_bfloat16* __restrict__ Ahi, const __nv_bfloat16* __restrict__ Alo,
    const __nv_bfloat16* __restrict__ Bhi, const __nv_bfloat16* __restrict__ Blo,
    const float* __restrict__ bias, float* __restrict__ Cf,
    __nv_bfloat16* __restrict__ Ch, __nv_bfloat16* __restrict__ Cl, int ldc)
{
    extern __shared__ __nv_bfloat16 smg[];

    int tid  = threadIdx.x;
    int lane = tid & 31, wid = tid >> 5;
    int wm = wid >> 2, wn = wid & 3;
    int bm = blockIdx.y * 128, bn = blockIdx.x * 128;

    const __nv_bfloat16* gsrc[4] = {Ahi, Alo, Bhi, Blo};
    int gbase[4] = {bm, bm, bn, bn};

    float acc[4][4][4];
#pragma unroll
    for (int i = 0; i < 4; i++)
#pragma unroll
        for (int j = 0; j < 4; j++)
#pragma unroll
            for (int q = 0; q < 4; q++) acc[i][j][q] = 0.f;

    int a_row = wm * 64 + (lane & 15);
    int a_kof = (lane >> 4) << 3;
    int b_row = wn * 32 + ((lane >> 4) << 3) + (lane & 7);
    int b_kof = ((lane >> 3) & 1) << 3;

    int lr = tid >> 2, ls = tid & 3;

    {
        __nv_bfloat16* s = smg;
#pragma unroll
        for (int hh = 0; hh < 8; hh++) {
            int pl = hh >> 1;
            int r  = ((hh & 1) << 6) + lr;
            size_t go = (size_t)(gbase[pl] + r) * 256 + ls * 8;
            cp_async16(smem_to_u32(s + pl * PLANE_E + r * ASTRIDE + ls * 8),
                       gsrc[pl] + go);
        }
        cp_commit();
    }

    for (int kt = 0; kt < 8; kt++) {
        int cur = kt & 1;
        if (kt < 7) {
            __nv_bfloat16* s = smg + (cur ^ 1) * TILE_E;
#pragma unroll
            for (int hh = 0; hh < 8; hh++) {
                int pl = hh >> 1;
                int r  = ((hh & 1) << 6) + lr;
                size_t go = (size_t)(gbase[pl] + r) * 256 + (kt + 1) * 32 + ls * 8;
                cp_async16(smem_to_u32(s + pl * PLANE_E + r * ASTRIDE + ls * 8),
                           gsrc[pl] + go);
            }
            cp_commit();
            cp_wait<1>();
        } else {
            cp_wait<0>();
        }
        __syncthreads();

        __nv_bfloat16* s = smg + cur * TILE_E;
        __nv_bfloat16* sAh = s;
        __nv_bfloat16* sAl = s + PLANE_E;
        __nv_bfloat16* sBh = s + 2 * PLANE_E;
        __nv_bfloat16* sBl = s + 3 * PLANE_E;

#pragma unroll
        for (int ks = 0; ks < 2; ks++) {
            int kk = ks * 16;
            uint32_t af[4][4], bh[2][4], bl[2][4];
#pragma unroll
            for (int i = 0; i < 4; i++)
                ldsm_x4(smem_to_u32(sAh + (a_row + i * 16) * ASTRIDE + kk + a_kof),
                        af[i][0], af[i][1], af[i][2], af[i][3]);
#pragma unroll
            for (int jj = 0; jj < 2; jj++) {
                ldsm_x4(smem_to_u32(sBh + (b_row + jj * 16) * ASTRIDE + kk + b_kof),
                        bh[jj][0], bh[jj][1], bh[jj][2], bh[jj][3]);
                ldsm_x4(smem_to_u32(sBl + (b_row + jj * 16) * ASTRIDE + kk + b_kof),
                        bl[jj][0], bl[jj][1], bl[jj][2], bl[jj][3]);
            }
#pragma unroll
            for (int i = 0; i < 4; i++)
#pragma unroll
                for (int j = 0; j < 4; j++) {
                    mma_bf16(acc[i][j], af[i], bh[j >> 1][(j & 1) * 2], bh[j >> 1][(j & 1) * 2 + 1]);
                    mma_bf16(acc[i][j], af[i], bl[j >> 1][(j & 1) * 2], bl[j >> 1][(j & 1) * 2 + 1]);
                }
#pragma unroll
            for (int i = 0; i < 4; i++)
                ldsm_x4(smem_to_u32(sAl + (a_row + i * 16) * ASTRIDE + kk + a_kof),
                        af[i][0], af[i][1], af[i][2], af[i][3]);
#pragma unroll
            for (int i = 0; i < 4; i++)
#pragma unroll
                for (int j = 0; j < 4; j++)
                    mma_bf16(acc[i][j], af[i], bh[j >> 1][(j & 1) * 2], bh[j >> 1][(j & 1) * 2 + 1]);
        }
        __syncthreads();
    }

    int er = lane >> 2, ec = (lane & 3) * 2;
#pragma unroll
    for (int i = 0; i < 4; i++) {
#pragma unroll
        for (int j = 0; j < 4; j++) {
            int row0 = bm + wm * 64 + i * 16 + er;
            int col  = bn + wn * 32 + j * 8 + ec;
            if (Cf) {
                float bx = 0.f, by = 0.f;
                if (bias) { bx = bias[col]; by = bias[col + 1]; }
                *(float2*)(Cf + (size_t)row0 * ldc + col) =
                    make_float2(acc[i][j][0] + bx, acc[i][j][1] + by);
                *(float2*)(Cf + (size_t)(row0 + 8) * ldc + col) =
                    make_float2(acc[i][j][2] + bx, acc[i][j][3] + by);
            } else {
                float r0, r1;
                uint32_t hi0 = pack_split(acc[i][j][0], acc[i][j][1], r0, r1);
                *(uint32_t*)(Ch + (size_t)row0 * ldc + col) = hi0;
                *(uint32_t*)(Cl + (size_t)row0 * ldc + col) = pack2(r0, r1);
                uint32_t hi1 = pack_split(acc[i][j][2], acc[i][j][3], r0, r1);
                *(uint32_t*)(Ch + (size_t)(row0 + 8) * ldc + col) = hi1;
                *(uint32_t*)(Cl + (size_t)(row0 + 8) * ldc + col) = pack2(r0, r1);
            }
        }
    }
}

// ---------------------------------------------------------------------------
// Kernel 3: FA2-style attention, R6 inner structure, split 2 CTAs per patch.
// CTA = (patch, head-group of 4). 128 threads = 4 warps = 1 warp per head,
// each warp loops all 4 q-blocks (the R6-proven schedule).
// smem: 5 half-width planes (Qh, Kh, Vh, Ql, Vl), 64 x 136 bf16 each = 87 KB
// -> 2 CTAs/SM. Stride 136 has the same mod-32 bank math as 264: conflict-free.
// ---------------------------------------------------------------------------
#define HS   136
#define PLNH (64 * HS)
#define ATTN_SM_BYTES (5 * PLNH * 2)   // 87040 B

__global__ __launch_bounds__(128) void k_attn_mma(
    const __nv_bfloat16* __restrict__ qkvh, const __nv_bfloat16* __restrict__ qkvl,
    __nv_bfloat16* __restrict__ ohi, __nv_bfloat16* __restrict__ olo)
{
    extern __shared__ __nv_bfloat16 sm[];
    // planes: 0=Qh 1=Kh 2=Vh 3=Ql 4=Vl (Kl never read by the math)
    int p = blockIdx.x >> 1, hg = blockIdx.x & 1;   // head group: cols hg*128..+128
    int tid = threadIdx.x;
    {
        const uint4* sh = (const uint4*)(qkvh + (size_t)p * 64 * 768);
        const uint4* sl = (const uint4*)(qkvl + (size_t)p * 64 * 768);
        // hi planes: 64 rows x 3 sections x 16 uint4
        for (int i = tid; i < 3072; i += 128) {
            int r = i / 48, rem = i - r * 48;
            int sec = rem >> 4, u = rem & 15;
            *(uint4*)(sm + sec * PLNH + r * HS + u * 8) =
                sh[r * 96 + sec * 32 + hg * 16 + u];
        }
        // lo planes: Q (sec 0 -> plane 3), V (sec 2 -> plane 4)
        for (int i = tid; i < 2048; i += 128) {
            int r = i >> 5, rem = i & 31;
            int s2 = rem >> 4, u = rem & 15;        // s2: 0=Q, 1=V
            *(uint4*)(sm + (3 + s2) * PLNH + r * HS + u * 8) =
                sl[r * 96 + (s2 * 2) * 32 + hg * 16 + u];
        }
    }
    __syncthreads();

    int lane = tid & 31, h = tid >> 5;   // local head 0..3
    int hbl = h * 32;                    // column base within half-planes
    int hgl = hg * 128 + hbl;            // global channel base
    int gr = lane >> 2, gc = (lane & 3) * 2;

    uint32_t base = smem_to_u32(sm);
    int a_r = lane & 15;
    int a_c = (lane >> 4) << 3;
    int b_r = ((lane >> 4) << 3) + (lane & 7);
    int b_c = ((lane >> 3) & 1) << 3;
    int v_r = (((lane >> 3) & 1) << 3) + (lane & 7);
    int v_c = (lane >> 4) << 3;

    for (int qb = 0; qb < 4; qb++) {
        float s[8][4];
#pragma unroll
        for (int j = 0; j < 8; j++)
#pragma unroll
            for (int q = 0; q < 4; q++) s[j][q] = 0.f;

        // ---- S = (Qh+Ql) @ Kh^T ----
#pragma unroll
        for (int kk = 0; kk < 2; kk++) {
            uint32_t aH[4], aL[4];
            uint32_t qoff = (uint32_t)((qb * 16 + a_r) * HS + hbl + kk * 16 + a_c) * 2;
            ldsm_x4(base + 0 * PLNH * 2 + qoff, aH[0], aH[1], aH[2], aH[3]);
            ldsm_x4(base + 3 * PLNH * 2 + qoff, aL[0], aL[1], aL[2], aL[3]);
#pragma unroll
            for (int jp = 0; jp < 4; jp++) {
                uint32_t kf[4];
                uint32_t koff = (uint32_t)((jp * 16 + b_r) * HS + hbl + kk * 16 + b_c) * 2;
                ldsm_x4(base + 1 * PLNH * 2 + koff, kf[0], kf[1], kf[2], kf[3]);
                mma_bf16(s[2 * jp],     aH, kf[0], kf[1]);
                mma_bf16(s[2 * jp + 1], aH, kf[2], kf[3]);
                mma_bf16(s[2 * jp],     aL, kf[0], kf[1]);
                mma_bf16(s[2 * jp + 1], aL, kf[2], kf[3]);
            }
        }

        // ---- softmax ----
        float mx0 = -1e30f, mx1 = -1e30f;
#pragma unroll
        for (int j = 0; j < 8; j++) {
#pragma unroll
            for (int q = 0; q < 4; q++) s[j][q] *= SCALE_ATT;
            mx0 = fmaxf(mx0, fmaxf(s[j][0], s[j][1]));
            mx1 = fmaxf(mx1, fmaxf(s[j][2], s[j][3]));
        }
        mx0 = fmaxf(mx0, __shfl_xor_sync(0xffffffffu, mx0, 1));
        mx0 = fmaxf(mx0, __shfl_xor_sync(0xffffffffu, mx0, 2));
        mx1 = fmaxf(mx1, __shfl_xor_sync(0xffffffffu, mx1, 1));
        mx1 = fmaxf(mx1, __shfl_xor_sync(0xffffffffu, mx1, 2));
        float sum0 = 0.f, sum1 = 0.f;
#pragma unroll
        for (int j = 0; j < 8; j++) {
            s[j][0] = __expf(s[j][0] - mx0);
            s[j][1] = __expf(s[j][1] - mx0);
            s[j][2] = __expf(s[j][2] - mx1);
            s[j][3] = __expf(s[j][3] - mx1);
            sum0 += s[j][0] + s[j][1];
            sum1 += s[j][2] + s[j][3];
        }
        sum0 += __shfl_xor_sync(0xffffffffu, sum0, 1);
        sum0 += __shfl_xor_sync(0xffffffffu, sum0, 2);
        sum1 += __shfl_xor_sync(0xffffffffu, sum1, 1);
        sum1 += __shfl_xor_sync(0xffffffffu, sum1, 2);

        // ---- O = P @ V (3 split products) ----
        float o[4][4];
#pragma unroll
        for (int t = 0; t < 4; t++)
#pragma unroll
            for (int q = 0; q < 4; q++) o[t][q] = 0.f;

#pragma unroll
        for (int kk = 0; kk < 4; kk++) {
            uint32_t ph[4], pl[4];
            float r0, r1;
            ph[0] = pack_split(s[2 * kk][0],     s[2 * kk][1],     r0, r1); pl[0] = pack2(r0, r1);
            ph[1] = pack_split(s[2 * kk][2],     s[2 * kk][3],     r0, r1); pl[1] = pack2(r0, r1);
            ph[2] = pack_split(s[2 * kk + 1][0], s[2 * kk + 1][1], r0, r1); pl[2] = pack2(r0, r1);
            ph[3] = pack_split(s[2 * kk + 1][2], s[2 * kk + 1][3], r0, r1); pl[3] = pack2(r0, r1);

            uint32_t vh[8], vl[8];
            uint32_t voff0 = (uint32_t)((kk * 16 + v_r) * HS + hbl + v_c) * 2;
            uint32_t voff1 = (uint32_t)((kk * 16 + v_r) * HS + hbl + 16 + v_c) * 2;
            ldsm_x4_t(base + 2 * PLNH * 2 + voff0, vh);
            ldsm_x4_t(base + 2 * PLNH * 2 + voff1, vh + 4);
            ldsm_x4_t(base + 4 * PLNH * 2 + voff0, vl);
            ldsm_x4_t(base + 4 * PLNH * 2 + voff1, vl + 4);
#pragma unroll
            for (int t = 0; t < 4; t++) {
                mma_bf16(o[t], ph, vh[2 * t], vh[2 * t + 1]);
                mma_bf16(o[t], ph, vl[2 * t], vl[2 * t + 1]);
                mma_bf16(o[t], pl, vh[2 * t], vh[2 * t + 1]);
            }
        }

        float inv0 = 1.f / sum0, inv1 = 1.f / sum1;
        size_t row0 = (size_t)(p * 64 + qb * 16 + gr) * 256 + hgl;
        size_t row1 = row0 + 8 * 256;
#pragma unroll
        for (int t = 0; t < 4; t++) {
            int col = t * 8 + gc;
            float r0, r1;
            uint32_t hi0 = pack_split(o[t][0] * inv0, o[t][1] * inv0, r0, r1);
            *(uint32_t*)(ohi + row0 + col) = hi0;
            *(uint32_t*)(olo + row0 + col) = pack2(r0, r1);
            uint32_t hi1 = pack_split(o[t][2] * inv1, o[t][3] * inv1, r0, r1);
            *(uint32_t*)(ohi + row1 + col) = hi1;
            *(uint32_t*)(olo + row1 + col) = pack2(r0, r1);
        }
    }
}

// ---------------------------------------------------------------------------
// Kernel 5: deterministic overlap-gather + count normalization.
// ---------------------------------------------------------------------------
__global__ __launch_bounds__(256) void k_scatter(
    const float* __restrict__ y, float* __restrict__ out)
{
    int pix = blockIdx.x;
    int ch  = threadIdx.x;
    int b = pix >> 12;
    int r = (pix >> 6) & 63;
    int c = pix & 63;

    int ph_lo = max(0, (r - 4) >> 2);
    int ph_hi = min(14, r >> 2);
    int pw_lo = max(0, (c - 4) >> 2);
    int pw_hi = min(14, c >> 2);

    float acc = 0.f;
    for (int ph = ph_lo; ph <= ph_hi; ph++) {
        for (int pw = pw_lo; pw <= pw_hi; pw++) {
            int p = b * 225 + ph * 15 + pw;
            int t = (r - ph * 4) * 8 + (c - pw * 4);
            acc += y[((size_t)p * 64 + t) * 256 + ch];
        }
    }
    float cnt = (float)((ph_hi - ph_lo + 1) * (pw_hi - pw_lo + 1));
    out[(size_t)pix * 256 + ch] = acc * (1.f / cnt);
}

// ---------------------------------------------------------------------------
// Entry point
// ---------------------------------------------------------------------------
extern "C" void kernel_launch(void* const* d_in, const int* in_sizes, int n_in,
                              void* d_out, int out_size)
{
    const float* x    = (const float*)d_in[0];
    const float* g1   = (const float*)d_in[1];
    const float* b1   = (const float*)d_in[2];
    const float* g2   = (const float*)d_in[3];
    const float* b2   = (const float*)d_in[4];
    const float* wqkv = (const float*)d_in[5];
    const float* wout = (const float*)d_in[6];
    const float* bout = (const float*)d_in[7];
    float* out = (float*)d_out;

    __nv_bfloat16 *qh, *ql, *phi, *plo, *wqh, *wql, *woh, *wol;
    cudaGetSymbolAddress((void**)&qh,  g_qh);
    cudaGetSymbolAddress((void**)&ql,  g_ql);
    cudaGetSymbolAddress((void**)&phi, g_phi);
    cudaGetSymbolAddress((void**)&plo, g_plo);
    cudaGetSymbolAddress((void**)&wqh, g_wqT_hi);
    cudaGetSymbolAddress((void**)&wql, g_wqT_lo);
    cudaGetSymbolAddress((void**)&woh, g_woT_hi);
    cudaGetSymbolAddress((void**)&wol, g_woT_lo);

    float* ybuf = (float*)qh;   // qkv planes dead after attention

    cudaFuncSetAttribute(k_attn_mma, cudaFuncAttributeMaxDynamicSharedMemorySize,
                         ATTN_SM_BYTES);
    cudaFuncSetAttribute(k_mma_gemm, cudaFuncAttributeMaxDynamicSharedMemorySize,
                         GEMM_SM_BYTES);

    k_split_w<<<(QKVDIM * CDIM + CDIM * CDIM + 255) / 256, 256>>>(
        wqkv, wout, wqh, wql, woh, wol);
    k_gather_ln<<<MROWS / 8, 256>>>(x, g1, b1, g2, b2, phi, plo);
    k_mma_gemm<<<dim3(QKVDIM / 128, MROWS / 128), 256, GEMM_SM_BYTES>>>(
        phi, plo, wqh, wql, nullptr, nullptr, qh, ql, QKVDIM);
    k_attn_mma<<<NPATCH * 2, 128, ATTN_SM_BYTES>>>(qh, ql, phi, plo);
    k_mma_gemm<<<dim3(CDIM / 128, MROWS / 128), 256, GEMM_SM_BYTES>>>(
        phi, plo, woh, wol, bout, ybuf, nullptr, nullptr, CDIM);
    k_scatter<<<8 * 64 * 64, 256>>>(ybuf, out);
}

// round 10
// speedup vs baseline: 1.2372x; 1.2372x over previous
#include <cuda_runtime.h>
#include <cuda_fp16.h>
#include <cstdint>
#include <math.h>

// ---------------------------------------------------------------------------
// Problem constants
// ---------------------------------------------------------------------------
#define NPATCH 1800            // B(8) * L(225)
#define NTOK   64              // k*k
#define CDIM   256
#define QKVDIM 768
#define MROWS  (NPATCH * NTOK) // 115200
#define SCALE_ATT 0.17677669529663687f

// ---------------------------------------------------------------------------
// Global scratch (fp16 planes).
//  g_qh/g_ql : qkv hi/lo (GEMM1 out / attn in); g_qh reused (as float*) for y.
//  g_phi/g_plo : h hi/lo (LN out / GEMM1 A), then o hi/lo (attn out / GEMM2 A)
// ---------------------------------------------------------------------------
__device__ __half  g_qh[(size_t)MROWS * QKVDIM];   // 177 MB
__device__ __half  g_ql[(size_t)MROWS * QKVDIM];   // 177 MB
__device__ __half  g_phi[(size_t)MROWS * CDIM];    // 59 MB
__device__ __half  g_plo[(size_t)MROWS * CDIM];    // 59 MB
__device__ __half  g_wqT_hi[QKVDIM * CDIM];
__device__ __half  g_wqT_lo[QKVDIM * CDIM];
__device__ __half  g_woT_hi[CDIM * CDIM];
__device__ __half  g_woT_lo[CDIM * CDIM];

// ---------------------------------------------------------------------------
// Helpers
// ---------------------------------------------------------------------------
__device__ __forceinline__ uint32_t smem_to_u32(const void* p) {
    uint32_t a;
    asm("{ .reg .u64 t; cvta.to.shared.u64 t, %1; cvt.u32.u64 %0, t; }"
        : "=r"(a) : "l"(p));
    return a;
}
__device__ __forceinline__ float warp_sum(float v) {
#pragma unroll
    for (int o = 16; o; o >>= 1) v += __shfl_xor_sync(0xffffffffu, v, o);
    return v;
}
__device__ __forceinline__ void split_h(float v, __half& hi, __half& lo) {
    hi = __float2half_rn(v);
    lo = __float2half_rn(v - __half2float(hi));
}
__device__ __forceinline__ void ldsm_x4(uint32_t addr, uint32_t& r0, uint32_t& r1,
                                        uint32_t& r2, uint32_t& r3) {
    asm volatile("ldmatrix.sync.aligned.m8n8.x4.shared.b16 {%0,%1,%2,%3}, [%4];"
                 : "=r"(r0), "=r"(r1), "=r"(r2), "=r"(r3) : "r"(addr));
}
__device__ __forceinline__ void ldsm_x4_t(uint32_t addr, uint32_t* r) {
    asm volatile("ldmatrix.sync.aligned.m8n8.x4.trans.shared.b16 {%0,%1,%2,%3}, [%4];"
                 : "=r"(r[0]), "=r"(r[1]), "=r"(r[2]), "=r"(r[3]) : "r"(addr));
}
__device__ __forceinline__ void mma_f16(float* d, const uint32_t* a,
                                        uint32_t b0, uint32_t b1) {
    asm volatile(
        "mma.sync.aligned.m16n8k16.row.col.f32.f16.f16.f32 "
        "{%0,%1,%2,%3}, {%4,%5,%6,%7}, {%8,%9}, {%0,%1,%2,%3};"
        : "+f"(d[0]), "+f"(d[1]), "+f"(d[2]), "+f"(d[3])
        : "r"(a[0]), "r"(a[1]), "r"(a[2]), "r"(a[3]), "r"(b0), "r"(b1));
}
__device__ __forceinline__ uint32_t pack_split(float c0, float c1, float& r0, float& r1) {
    __half2 t = __floats2half2_rn(c0, c1);   // .x = c0
    r0 = c0 - __half2float(t.x);
    r1 = c1 - __half2float(t.y);
    return *reinterpret_cast<uint32_t*>(&t);
}
__device__ __forceinline__ uint32_t pack2(float c0, float c1) {
    __half2 t = __floats2half2_rn(c0, c1);
    return *reinterpret_cast<uint32_t*>(&t);
}
__device__ __forceinline__ void cp_async16(uint32_t saddr, const void* gaddr) {
    asm volatile("cp.async.cg.shared.global [%0], [%1], 16;" :: "r"(saddr), "l"(gaddr));
}
__device__ __forceinline__ void cp_commit() {
    asm volatile("cp.async.commit_group;" ::: "memory");
}
template<int N>
__device__ __forceinline__ void cp_wait() {
    asm volatile("cp.async.wait_group %0;" :: "n"(N) : "memory");
}

// ---------------------------------------------------------------------------
// Kernel 0: transpose + hi/lo split of the two weight matrices
// ---------------------------------------------------------------------------
__global__ __launch_bounds__(256) void k_split_w(
    const float* __restrict__ wqkv, const float* __restrict__ wout,
    __half* __restrict__ qT_hi, __half* __restrict__ qT_lo,
    __half* __restrict__ oT_hi, __half* __restrict__ oT_lo)
{
    int e = blockIdx.x * 256 + threadIdx.x;
    if (e < QKVDIM * CDIM) {
        int n = e >> 8, k = e & 255;
        __half h, l;
        split_h(wqkv[k * QKVDIM + n], h, l);
        qT_hi[e] = h; qT_lo[e] = l;
    } else {
        int e2 = e - QKVDIM * CDIM;
        if (e2 < CDIM * CDIM) {
            int n = e2 >> 8, k = e2 & 255;
            __half h, l;
            split_h(wout[k * CDIM + n], h, l);
            oT_hi[e2] = h; oT_lo[e2] = l;
        }
    }
}

// ---------------------------------------------------------------------------
// Kernel 1: gather patches + LayerNorm x2, emit hi/lo fp16 planes
// ---------------------------------------------------------------------------
__global__ __launch_bounds__(256) void k_gather_ln(
    const float* __restrict__ x,
    const float* __restrict__ g1, const float* __restrict__ b1,
    const float* __restrict__ g2, const float* __restrict__ b2,
    __half* __restrict__ hhi, __half* __restrict__ hlo)
{
    int warp = threadIdx.x >> 5, lane = threadIdx.x & 31;
    int row = blockIdx.x * 8 + warp;
    int p = row >> 6, t = row & 63;
    int b = p / 225, l = p - b * 225;
    int ph = l / 15, pw = l - ph * 15;
    int gr = ph * 4 + (t >> 3);
    int gc = pw * 4 + (t & 7);
    const float* xr = x + (((size_t)(b * 64 + gr)) * 64 + gc) * 256;

    float v[8];
    float s = 0.f;
#pragma unroll
    for (int i = 0; i < 8; i++) { v[i] = xr[lane + i * 32]; s += v[i]; }
    s = warp_sum(s);
    float mean = s * (1.f / 256.f);
    float vs = 0.f;
#pragma unroll
    for (int i = 0; i < 8; i++) { v[i] -= mean; vs += v[i] * v[i]; }
    vs = warp_sum(vs);
    float inv = rsqrtf(vs * (1.f / 256.f) + 1e-5f);

    float s2 = 0.f;
#pragma unroll
    for (int i = 0; i < 8; i++) {
        v[i] = v[i] * inv * g1[lane + i * 32] + b1[lane + i * 32];
        s2 += v[i];
    }
    s2 = warp_sum(s2);
    float mean2 = s2 * (1.f / 256.f);
    float vs2 = 0.f;
#pragma unroll
    for (int i = 0; i < 8; i++) { v[i] -= mean2; vs2 += v[i] * v[i]; }
    vs2 = warp_sum(vs2);
    float inv2 = rsqrtf(vs2 * (1.f / 256.f) + 1e-5f);

    size_t base = (size_t)row * 256;
#pragma unroll
    for (int i = 0; i < 8; i++) {
        float val = v[i] * inv2 * g2[lane + i * 32] + b2[lane + i * 32];
        __half h, lo;
        split_h(val, h, lo);
        hhi[base + lane + i * 32] = h;
        hlo[base + lane + i * 32] = lo;
    }
}

// ---------------------------------------------------------------------------
// mma.sync fp16 GEMM, cp.async double-buffered.
// NPROD=3: C = (Ahi+Alo) @ (Bhi+Blo)^T  (products ah*bh, ah*bl, al*bh)
// NPROD=2: C = (Ahi+Alo) @ Bhi^T        (Bl plane never loaded; err ~2^-12)
// ---------------------------------------------------------------------------
#define ASTRIDE 40
#define PLANE_E (128 * ASTRIDE)
#define TILE_E  (4 * PLANE_E)
#define GEMM_SM_BYTES (2 * TILE_E * 2) // 81920 B

template<int NPROD>
__global__ __launch_bounds__(256, 2) void k_mma_gemm(
    const __half* __restrict__ Ahi, const __half* __restrict__ Alo,
    const __half* __restrict__ Bhi, const __half* __restrict__ Blo,
    const float* __restrict__ bias, float* __restrict__ Cf,
    __half* __restrict__ Ch, __half* __restrict__ Cl, int ldc)
{
    extern __shared__ __half smg[];

    int tid  = threadIdx.x;
    int lane = tid & 31, wid = tid >> 5;
    int wm = wid >> 2, wn = wid & 3;
    int bm = blockIdx.y * 128, bn = blockIdx.x * 128;

    const __half* gsrc[4] = {Ahi, Alo, Bhi, Blo};
    int gbase[4] = {bm, bm, bn, bn};

    float acc[4][4][4];
#pragma unroll
    for (int i = 0; i < 4; i++)
#pragma unroll
        for (int j = 0; j < 4; j++)
#pragma unroll
            for (int q = 0; q < 4; q++) acc[i][j][q] = 0.f;

    int a_row = wm * 64 + (lane & 15);
    int a_kof = (lane >> 4) << 3;
    int b_row = wn * 32 + ((lane >> 4) << 3) + (lane & 7);
    int b_kof = ((lane >> 3) & 1) << 3;

    int lr = tid >> 2, ls = tid & 3;

    {
        __half* s = smg;
#pragma unroll
        for (int hh = 0; hh < 8; hh++) {
            int pl = hh >> 1;
            if (NPROD == 2 && pl == 3) continue;
            int r  = ((hh & 1) << 6) + lr;
            size_t go = (size_t)(gbase[pl] + r) * 256 + ls * 8;
            cp_async16(smem_to_u32(s + pl * PLANE_E + r * ASTRIDE + ls * 8),
                       gsrc[pl] + go);
        }
        cp_commit();
    }

    for (int kt = 0; kt < 8; kt++) {
        int cur = kt & 1;
        if (kt < 7) {
            __half* s = smg + (cur ^ 1) * TILE_E;
#pragma unroll
            for (int hh = 0; hh < 8; hh++) {
                int pl = hh >> 1;
                if (NPROD == 2 && pl == 3) continue;
                int r  = ((hh & 1) << 6) + lr;
                size_t go = (size_t)(gbase[pl] + r) * 256 + (kt + 1) * 32 + ls * 8;
                cp_async16(smem_to_u32(s + pl * PLANE_E + r * ASTRIDE + ls * 8),
                           gsrc[pl] + go);
            }
            cp_commit();
            cp_wait<1>();
        } else {
            cp_wait<0>();
        }
        __syncthreads();

        __half* s = smg + cur * TILE_E;
        __half* sAh = s;
        __half* sAl = s + PLANE_E;
        __half* sBh = s + 2 * PLANE_E;
        __half* sBl = s + 3 * PLANE_E;

#pragma unroll
        for (int ks = 0; ks < 2; ks++) {
            int kk = ks * 16;
            uint32_t af[4][4], bh[2][4], bl[2][4];
#pragma unroll
            for (int i = 0; i < 4; i++)
                ldsm_x4(smem_to_u32(sAh + (a_row + i * 16) * ASTRIDE + kk + a_kof),
                        af[i][0], af[i][1], af[i][2], af[i][3]);
#pragma unroll
            for (int jj = 0; jj < 2; jj++) {
                ldsm_x4(smem_to_u32(sBh + (b_row + jj * 16) * ASTRIDE + kk + b_kof),
                        bh[jj][0], bh[jj][1], bh[jj][2], bh[jj][3]);
                if (NPROD == 3)
                    ldsm_x4(smem_to_u32(sBl + (b_row + jj * 16) * ASTRIDE + kk + b_kof),
                            bl[jj][0], bl[jj][1], bl[jj][2], bl[jj][3]);
            }
#pragma unroll
            for (int i = 0; i < 4; i++)
#pragma unroll
                for (int j = 0; j < 4; j++) {
                    mma_f16(acc[i][j], af[i], bh[j >> 1][(j & 1) * 2], bh[j >> 1][(j & 1) * 2 + 1]);
                    if (NPROD == 3)
                        mma_f16(acc[i][j], af[i], bl[j >> 1][(j & 1) * 2], bl[j >> 1][(j & 1) * 2 + 1]);
                }
#pragma unroll
            for (int i = 0; i < 4; i++)
                ldsm_x4(smem_to_u32(sAl + (a_row + i * 16) * ASTRIDE + kk + a_kof),
                        af[i][0], af[i][1], af[i][2], af[i][3]);
#pragma unroll
            for (int i = 0; i < 4; i++)
#pragma unroll
                for (int j = 0; j < 4; j++)
                    mma_f16(acc[i][j], af[i], bh[j >> 1][(j & 1) * 2], bh[j >> 1][(j & 1) * 2 + 1]);
        }
        __syncthreads();
    }

    int er = lane >> 2, ec = (lane & 3) * 2;
#pragma unroll
    for (int i = 0; i < 4; i++) {
#pragma unroll
        for (int j = 0; j < 4; j++) {
            int row0 = bm + wm * 64 + i * 16 + er;
            int col  = bn + wn * 32 + j * 8 + ec;
            if (Cf) {
                float bx = 0.f, by = 0.f;
                if (bias) { bx = bias[col]; by = bias[col + 1]; }
                *(float2*)(Cf + (size_t)row0 * ldc + col) =
                    make_float2(acc[i][j][0] + bx, acc[i][j][1] + by);
                *(float2*)(Cf + (size_t)(row0 + 8) * ldc + col) =
                    make_float2(acc[i][j][2] + bx, acc[i][j][3] + by);
            } else {
                float r0, r1;
                uint32_t hi0 = pack_split(acc[i][j][0], acc[i][j][1], r0, r1);
                *(uint32_t*)(Ch + (size_t)row0 * ldc + col) = hi0;
                *(uint32_t*)(Cl + (size_t)row0 * ldc + col) = pack2(r0, r1);
                uint32_t hi1 = pack_split(acc[i][j][2], acc[i][j][3], r0, r1);
                *(uint32_t*)(Ch + (size_t)(row0 + 8) * ldc + col) = hi1;
                *(uint32_t*)(Cl + (size_t)(row0 + 8) * ldc + col) = pack2(r0, r1);
            }
        }
    }
}

// ---------------------------------------------------------------------------
// Kernel 3: FA2-style per-patch attention — EXACT R6 structure (measured
// best: 188us), fp16 dtype. 1 CTA = 1 patch, 256 threads, warp = head,
// each warp loops 4 q-blocks. Planes Qh,Kh,Vh,Ql,Kl,Vl, 64x264, stride 528B.
// ---------------------------------------------------------------------------
#define QS  264
#define PLN (64 * QS)
#define ATTN_SM_BYTES (6 * PLN * 2)   // 202752 B

__global__ __launch_bounds__(256) void k_attn_mma(
    const __half* __restrict__ qkvh, const __half* __restrict__ qkvl,
    __half* __restrict__ ohi, __half* __restrict__ olo)
{
    extern __shared__ __half sm[];
    int p = blockIdx.x, tid = threadIdx.x;
    {
        const uint4* sh = (const uint4*)(qkvh + (size_t)p * 64 * 768);
        const uint4* sl = (const uint4*)(qkvl + (size_t)p * 64 * 768);
#pragma unroll 4
        for (int i = tid; i < 6144; i += 256) {
            int row = i / 96, cb = (i - row * 96) * 8;
            int sec = cb >> 8, cc = cb & 255;
            int d = sec * PLN + row * QS + cc;
            *(uint4*)(sm + d)           = sh[i];
            *(uint4*)(sm + 3 * PLN + d) = sl[i];
        }
    }
    __syncthreads();

    int lane = tid & 31, h = tid >> 5;
    int hb = h * 32;
    int gr = lane >> 2, gc = (lane & 3) * 2;

    uint32_t base = smem_to_u32(sm);
    int a_r = lane & 15;
    int a_c = (lane >> 4) << 3;
    int b_r = ((lane >> 4) << 3) + (lane & 7);
    int b_c = ((lane >> 3) & 1) << 3;
    int v_r = (((lane >> 3) & 1) << 3) + (lane & 7);
    int v_c = (lane >> 4) << 3;

    for (int qb = 0; qb < 4; qb++) {
        float s[8][4];
#pragma unroll
        for (int j = 0; j < 8; j++)
#pragma unroll
            for (int q = 0; q < 4; q++) s[j][q] = 0.f;

        // ---- S = (Qh+Ql) @ Kh^T ----
#pragma unroll
        for (int kk = 0; kk < 2; kk++) {
            uint32_t aH[4], aL[4];
            uint32_t qoff = (uint32_t)((qb * 16 + a_r) * QS + hb + kk * 16 + a_c) * 2;
            ldsm_x4(base + 0 * PLN * 2 + qoff, aH[0], aH[1], aH[2], aH[3]);
            ldsm_x4(base + 3 * PLN * 2 + qoff, aL[0], aL[1], aL[2], aL[3]);
#pragma unroll
            for (int jp = 0; jp < 4; jp++) {
                uint32_t kf[4];
                uint32_t koff = (uint32_t)((jp * 16 + b_r) * QS + hb + kk * 16 + b_c) * 2;
                ldsm_x4(base + 1 * PLN * 2 + koff, kf[0], kf[1], kf[2], kf[3]);
                mma_f16(s[2 * jp],     aH, kf[0], kf[1]);
                mma_f16(s[2 * jp + 1], aH, kf[2], kf[3]);
                mma_f16(s[2 * jp],     aL, kf[0], kf[1]);
                mma_f16(s[2 * jp + 1], aL, kf[2], kf[3]);
            }
        }

        // ---- softmax ----
        float mx0 = -1e30f, mx1 = -1e30f;
#pragma unroll
        for (int j = 0; j < 8; j++) {
#pragma unroll
            for (int q = 0; q < 4; q++) s[j][q] *= SCALE_ATT;
            mx0 = fmaxf(mx0, fmaxf(s[j][0], s[j][1]));
            mx1 = fmaxf(mx1, fmaxf(s[j][2], s[j][3]));
        }
        mx0 = fmaxf(mx0, __shfl_xor_sync(0xffffffffu, mx0, 1));
        mx0 = fmaxf(mx0, __shfl_xor_sync(0xffffffffu, mx0, 2));
        mx1 = fmaxf(mx1, __shfl_xor_sync(0xffffffffu, mx1, 1));
        mx1 = fmaxf(mx1, __shfl_xor_sync(0xffffffffu, mx1, 2));
        float sum0 = 0.f, sum1 = 0.f;
#pragma unroll
        for (int j = 0; j < 8; j++) {
            s[j][0] = __expf(s[j][0] - mx0);
            s[j][1] = __expf(s[j][1] - mx0);
            s[j][2] = __expf(s[j][2] - mx1);
            s[j][3] = __expf(s[j][3] - mx1);
            sum0 += s[j][0] + s[j][1];
            sum1 += s[j][2] + s[j][3];
        }
        sum0 += __shfl_xor_sync(0xffffffffu, sum0, 1);
        sum0 += __shfl_xor_sync(0xffffffffu, sum0, 2);
        sum1 += __shfl_xor_sync(0xffffffffu, sum1, 1);
        sum1 += __shfl_xor_sync(0xffffffffu, sum1, 2);

        // ---- O = P @ V (3 split products) ----
        float o[4][4];
#pragma unroll
        for (int t = 0; t < 4; t++)
#pragma unroll
            for (int q = 0; q < 4; q++) o[t][q] = 0.f;

#pragma unroll
        for (int kk = 0; kk < 4; kk++) {
            uint32_t ph[4], pl[4];
            float r0, r1;
            ph[0] = pack_split(s[2 * kk][0],     s[2 * kk][1],     r0, r1); pl[0] = pack2(r0, r1);
            ph[1] = pack_split(s[2 * kk][2],     s[2 * kk][3],     r0, r1); pl[1] = pack2(r0, r1);
            ph[2] = pack_split(s[2 * kk + 1][0], s[2 * kk + 1][1], r0, r1); pl[2] = pack2(r0, r1);
            ph[3] = pack_split(s[2 * kk + 1][2], s[2 * kk + 1][3], r0, r1); pl[3] = pack2(r0, r1);

            uint32_t vh[8], vl[8];
            uint32_t voff0 = (uint32_t)((kk * 16 + v_r) * QS + hb + v_c) * 2;
            uint32_t voff1 = (uint32_t)((kk * 16 + v_r) * QS + hb + 16 + v_c) * 2;
            ldsm_x4_t(base + 2 * PLN * 2 + voff0, vh);
            ldsm_x4_t(base + 2 * PLN * 2 + voff1, vh + 4);
            ldsm_x4_t(base + 5 * PLN * 2 + voff0, vl);
            ldsm_x4_t(base + 5 * PLN * 2 + voff1, vl + 4);
#pragma unroll
            for (int t = 0; t < 4; t++) {
                mma_f16(o[t], ph, vh[2 * t], vh[2 * t + 1]);
                mma_f16(o[t], ph, vl[2 * t], vl[2 * t + 1]);
                mma_f16(o[t], pl, vh[2 * t], vh[2 * t + 1]);
            }
        }

        float inv0 = 1.f / sum0, inv1 = 1.f / sum1;
        size_t row0 = (size_t)(p * 64 + qb * 16 + gr) * 256 + hb;
        size_t row1 = row0 + 8 * 256;
#pragma unroll
        for (int t = 0; t < 4; t++) {
            int col = t * 8 + gc;
            float r0, r1;
            uint32_t hi0 = pack_split(o[t][0] * inv0, o[t][1] * inv0, r0, r1);
            *(uint32_t*)(ohi + row0 + col) = hi0;
            *(uint32_t*)(olo + row0 + col) = pack2(r0, r1);
            uint32_t hi1 = pack_split(o[t][2] * inv1, o[t][3] * inv1, r0, r1);
            *(uint32_t*)(ohi + row1 + col) = hi1;
            *(uint32_t*)(olo + row1 + col) = pack2(r0, r1);
        }
    }
}

// ---------------------------------------------------------------------------
// Kernel 5: deterministic overlap-gather + count normalization.
// ---------------------------------------------------------------------------
__global__ __launch_bounds__(256) void k_scatter(
    const float* __restrict__ y, float* __restrict__ out)
{
    int pix = blockIdx.x;
    int ch  = threadIdx.x;
    int b = pix >> 12;
    int r = (pix >> 6) & 63;
    int c = pix & 63;

    int ph_lo = max(0, (r - 4) >> 2);
    int ph_hi = min(14, r >> 2);
    int pw_lo = max(0, (c - 4) >> 2);
    int pw_hi = min(14, c >> 2);

    float acc = 0.f;
    for (int ph = ph_lo; ph <= ph_hi; ph++) {
        for (int pw = pw_lo; pw <= pw_hi; pw++) {
            int p = b * 225 + ph * 15 + pw;
            int t = (r - ph * 4) * 8 + (c - pw * 4);
            acc += y[((size_t)p * 64 + t) * 256 + ch];
        }
    }
    float cnt = (float)((ph_hi - ph_lo + 1) * (pw_hi - pw_lo + 1));
    out[(size_t)pix * 256 + ch] = acc * (1.f / cnt);
}

// ---------------------------------------------------------------------------
// Entry point
// ---------------------------------------------------------------------------
extern "C" void kernel_launch(void* const* d_in, const int* in_sizes, int n_in,
                              void* d_out, int out_size)
{
    const float* x    = (const float*)d_in[0];
    const float* g1   = (const float*)d_in[1];
    const float* b1   = (const float*)d_in[2];
    const float* g2   = (const float*)d_in[3];
    const float* b2   = (const float*)d_in[4];
    const float* wqkv = (const float*)d_in[5];
    const float* wout = (const float*)d_in[6];
    const float* bout = (const float*)d_in[7];
    float* out = (float*)d_out;

    __half *qh, *ql, *phi, *plo, *wqh, *wql, *woh, *wol;
    cudaGetSymbolAddress((void**)&qh,  g_qh);
    cudaGetSymbolAddress((void**)&ql,  g_ql);
    cudaGetSymbolAddress((void**)&phi, g_phi);
    cudaGetSymbolAddress((void**)&plo, g_plo);
    cudaGetSymbolAddress((void**)&wqh, g_wqT_hi);
    cudaGetSymbolAddress((void**)&wql, g_wqT_lo);
    cudaGetSymbolAddress((void**)&woh, g_woT_hi);
    cudaGetSymbolAddress((void**)&wol, g_woT_lo);

    float* ybuf = (float*)qh;   // qkv planes dead after attention

    cudaFuncSetAttribute(k_attn_mma, cudaFuncAttributeMaxDynamicSharedMemorySize,
                         ATTN_SM_BYTES);
    cudaFuncSetAttribute(k_mma_gemm<2>, cudaFuncAttributeMaxDynamicSharedMemorySize,
                         GEMM_SM_BYTES);
    cudaFuncSetAttribute(k_mma_gemm<3>, cudaFuncAttributeMaxDynamicSharedMemorySize,
                         GEMM_SM_BYTES);

    k_split_w<<<(QKVDIM * CDIM + CDIM * CDIM + 255) / 256, 256>>>(
        wqkv, wout, wqh, wql, woh, wol);
    k_gather_ln<<<MROWS / 8, 256>>>(x, g1, b1, g2, b2, phi, plo);
    k_mma_gemm<2><<<dim3(QKVDIM / 128, MROWS / 128), 256, GEMM_SM_BYTES>>>(
        phi, plo, wqh, wql, nullptr, nullptr, qh, ql, QKVDIM);
    k_attn_mma<<<NPATCH, 256, ATTN_SM_BYTES>>>(qh, ql, phi, plo);
    k_mma_gemm<3><<<dim3(CDIM / 128, MROWS / 128), 256, GEMM_SM_BYTES>>>(
        phi, plo, woh, wol, bout, ybuf, nullptr, nullptr, CDIM);
    k_scatter<<<8 * 64 * 64, 256>>>(ybuf, out);
}